// round 13
// baseline (speedup 1.0000x reference)
#include <cuda_runtime.h>

#define NREL 8
#define NU   50000
#define ETOT 3400000
typedef long long ll;
typedef unsigned long long ull;

__constant__ int c_N[8]       = {50000,50000,10000,10000,10000,10000,10000,10000};
__constant__ int c_edgeoff[8] = {0,800000,1600000,1900000,2200000,2500000,2800000,3100000};
__constant__ int c_chunkoff[8]= {0,782,1564,1721,1878,2035,2192,2349};

// dynamic (types 0/1) double-buffered; static (types 2-7) single copy
__device__ float g_embD[2][100000*64];
__device__ float g_embS[60000*64];
__device__ float g_ssrc[2][NREL*NU*2];
__device__ float g_sdstD[2][2*NU*2];
__device__ float g_sdstS[60000*2];
__device__ int   g_rowptr[NREL*(NU+1)];
__device__ int   g_counts[NREL*NU];   // zero at load; re-zeroed by k_rezero each call
__device__ int   g_cursor[NREL*NU];
__device__ int   g_isorted[ETOT];

__device__ __forceinline__ float lrelu(float x){ return x > 0.f ? x : 0.2f*x; }
__device__ __forceinline__ float tanh_f(float x){
    float y; asm("tanh.approx.f32 %0, %1;" : "=f"(y) : "f"(x)); return y;
}

// ---------------- setup ----------------
__global__ void k_count_all(const int* __restrict__ u0, const int* __restrict__ u1,
                            const int* __restrict__ u2, const int* __restrict__ u3,
                            const int* __restrict__ u4, const int* __restrict__ u5,
                            const int* __restrict__ u6, const int* __restrict__ u7){
    int t = blockIdx.x*blockDim.x + threadIdx.x;
    if (t >= ETOT) return;
    int rel = 0;
    #pragma unroll
    for (int j=1;j<8;j++) if (t >= c_edgeoff[j]) rel = j;
    const int* up;
    switch (rel){
        case 0: up=u0; break; case 1: up=u1; break; case 2: up=u2; break; case 3: up=u3; break;
        case 4: up=u4; break; case 5: up=u5; break; case 6: up=u6; break; default: up=u7; break;
    }
    atomicAdd(&g_counts[rel*NU + up[t - c_edgeoff[rel]]], 1);
}

__global__ void k_scan(){
    __shared__ int sm[1024];
    int rel = blockIdx.x, t = threadIdx.x;
    const int n = NU, CH = 49;
    int* cnt = g_counts + rel*NU;
    int* rp  = g_rowptr + rel*(NU+1);
    int c0 = t*CH, c1 = min(c0+CH, n);
    int s = 0;
    for (int i=c0;i<c1;i++) s += cnt[i];
    sm[t] = s; __syncthreads();
    for (int off=1; off<1024; off<<=1){
        int v = (t>=off)? sm[t-off] : 0;
        __syncthreads();
        sm[t] += v;
        __syncthreads();
    }
    int run = sm[t] - s;
    for (int i=c0;i<c1;i++){ rp[i]=run; run+=cnt[i]; }
    if (t==0) rp[n] = sm[1023];
}

__global__ void k_scatter_all(const int* __restrict__ u0, const int* __restrict__ u1,
                              const int* __restrict__ u2, const int* __restrict__ u3,
                              const int* __restrict__ u4, const int* __restrict__ u5,
                              const int* __restrict__ u6, const int* __restrict__ u7,
                              const int* __restrict__ i0, const int* __restrict__ i1,
                              const int* __restrict__ i2, const int* __restrict__ i3,
                              const int* __restrict__ i4, const int* __restrict__ i5,
                              const int* __restrict__ i6, const int* __restrict__ i7){
    int t = blockIdx.x*blockDim.x + threadIdx.x;
    if (t >= ETOT) return;
    int rel = 0;
    #pragma unroll
    for (int j=1;j<8;j++) if (t >= c_edgeoff[j]) rel = j;
    const int *up, *ip;
    switch (rel){
        case 0: up=u0; ip=i0; break; case 1: up=u1; ip=i1; break;
        case 2: up=u2; ip=i2; break; case 3: up=u3; ip=i3; break;
        case 4: up=u4; ip=i4; break; case 5: up=u5; ip=i5; break;
        case 6: up=u6; ip=i6; break; default: up=u7; ip=i7; break;
    }
    int e = t - c_edgeoff[rel];
    int uu = up[e];
    int pos = g_rowptr[rel*(NU+1)+uu] + atomicAdd(&g_cursor[rel*NU+uu], 1);
    g_isorted[c_edgeoff[rel] + pos] = ip[e];
}

// initial projection: l2norm(lrelu(emb_t @ Wtk[t][k]))
__global__ void __launch_bounds__(256) k_proj(
    const float* __restrict__ e0, const float* __restrict__ e1,
    const float* __restrict__ e2, const float* __restrict__ e3,
    const float* __restrict__ e4, const float* __restrict__ e5,
    const float* __restrict__ e6, const float* __restrict__ e7,
    const float* __restrict__ Wtk)
{
    __shared__ float sW[4096];
    __shared__ float sE[4096];
    int b = blockIdx.x;
    int t = 0;
    #pragma unroll
    for (int j=1;j<8;j++) if (b >= c_chunkoff[j]) t = j;
    int n0 = (b - c_chunkoff[t]) * 64;
    const float* embp;
    switch (t){
        case 0: embp=e0; break; case 1: embp=e1; break;
        case 2: embp=e2; break; case 3: embp=e3; break;
        case 4: embp=e4; break; case 5: embp=e5; break;
        case 6: embp=e6; break; default: embp=e7; break;
    }
    int Nt = c_N[t], tid = threadIdx.x;
    for (int i=tid;i<4096;i+=256) sW[i] = Wtk[t*4096 + i];
    for (int i=tid;i<4096;i+=256){
        int n = n0 + (i>>6);
        sE[i] = (n < Nt) ? embp[(ll)n*64 + (i&63)] : 0.f;
    }
    __syncthreads();
    int lane = tid&31, w = tid>>5;
    float acc0[8], acc1[8];
    #pragma unroll
    for (int q=0;q<8;q++){ acc0[q]=0.f; acc1[q]=0.f; }
    #pragma unroll 4
    for (int c=0;c<64;c++){
        float w0 = sW[c*32+lane];
        float w1 = sW[2048+c*32+lane];
        #pragma unroll
        for (int q=0;q<8;q++){
            float e = sE[(w*8+q)*64 + c];
            acc0[q] = fmaf(e,w0,acc0[q]);
            acc1[q] = fmaf(e,w1,acc1[q]);
        }
    }
    #pragma unroll
    for (int q=0;q<8;q++){
        int n = n0 + w*8 + q;
        if (n >= Nt) continue;
        float y0 = lrelu(acc0[q]), y1 = lrelu(acc1[q]);
        float s0 = y0*y0, s1 = y1*y1;
        #pragma unroll
        for (int o=16;o;o>>=1){
            s0 += __shfl_xor_sync(0xffffffffu, s0, o);
            s1 += __shfl_xor_sync(0xffffffffu, s1, o);
        }
        float d0 = fmaxf(sqrtf(s0), 1e-12f);
        float d1 = fmaxf(sqrtf(s1), 1e-12f);
        float* dst;
        if (t < 2) dst = &g_embD[0][(t*NU + n)*64];
        else       dst = &g_embS[((t-2)*10000 + n)*64];
        dst[lane]      = y0 / d0;
        dst[32 + lane] = y1 / d1;
    }
}

// initial per-node attention dot halves (gen-0)
__global__ void k_dots0(const float* __restrict__ at){
    int lane = threadIdx.x & 31;
    int gw = (blockIdx.x*blockDim.x + threadIdx.x) >> 5;
    int k = lane >> 4, col = (lane&15)*2;
    float2 e; const float* ap; float* outp;
    if (gw < 400000){
        int rel = gw / NU, n = gw - rel*NU;
        int type = rel ? 1 : 0;
        e = *(const float2*)&g_embD[0][(type*NU+n)*64 + lane*2];
        ap = &at[(rel*2+k)*64 + col];
        outp = &g_ssrc[0][(rel*NU+n)*2 + k];
    } else if (gw < 450000){
        int n = gw - 400000;
        e = *(const float2*)&g_embD[0][(NU+n)*64 + lane*2];
        ap = &at[(0*2+k)*64 + 32 + col];
        outp = &g_sdstD[0][n*2 + k];
    } else if (gw < 500000){
        int n = gw - 450000;
        e = *(const float2*)&g_embD[0][n*64 + lane*2];
        ap = &at[(1*2+k)*64 + 32 + col];
        outp = &g_sdstD[0][NU*2 + n*2 + k];
    } else {
        int m = gw - 500000;
        e = *(const float2*)&g_embS[m*64 + lane*2];
        int rel = 2 + m/10000;
        ap = &at[(rel*2+k)*64 + 32 + col];
        outp = &g_sdstS[m*2 + k];
    }
    float p = e.x*__ldg(&ap[0]) + e.y*__ldg(&ap[1]);
    p += __shfl_xor_sync(0xffffffffu, p, 8);
    p += __shfl_xor_sync(0xffffffffu, p, 4);
    p += __shfl_xor_sync(0xffffffffu, p, 2);
    p += __shfl_xor_sync(0xffffffffu, p, 1);
    if ((lane&15) == 0) *outp = p;
}

// ---------------- fused iteration: block = node pair, warp = relation ----------------
// __launch_bounds__(256, 8): cap regs at 32 so 8 blocks (2048 thr) fit per SM.
__global__ void __launch_bounds__(256, 8) k_iter(const float* __restrict__ W,
                                                 const float* __restrict__ q,
                                                 const float* __restrict__ at,
                                                 int cur, int last,
                                                 float* __restrict__ out){
    if (blockIdx.x >= 50000){
        if (!last) return;
        // static types copy to output rows 100000..159999
        int base = (blockIdx.x - 50000)*1024 + threadIdx.x;
        float4* o4 = (float4*)(out + (ll)100000*64);
        #pragma unroll
        for (int j=0;j<4;j++){
            int i = base + j*256;
            if (i < 960000) o4[i] = ((const float4*)g_embS)[i];
        }
        return;
    }
    __shared__ float sW[1024];
    __shared__ float sZ[7][64];
    int tid = threadIdx.x;
    for (int i=tid;i<1024;i+=256) sW[i] = W[i];
    __syncthreads();
    int lane = tid&31, wl = tid>>5;
    int n = blockIdx.x;
    int nxt = cur ^ 1;
    int k = lane>>4, col = (lane&15)*2, basel = lane & 16;

    int rel = (wl == 7) ? 0 : (wl + 1);
    const float *de, *sdb;
    if (rel == 0){      de = &g_embD[cur][NU*64]; sdb = &g_sdstD[cur][0]; }
    else if (rel == 1){ de = &g_embD[cur][0];     sdb = &g_sdstD[cur][NU*2]; }
    else {              de = &g_embS[(rel-2)*10000*64]; sdb = &g_sdstS[(rel-2)*10000*2]; }

    float2 ss = *(const float2*)&g_ssrc[cur][(rel*NU+n)*2];
    int rb = rel*(NU+1) + n;
    int row = g_rowptr[rb], deg = g_rowptr[rb+1] - row;
    int eb = c_edgeoff[rel] + row;

    int g = lane >> 4, d = lane & 15;
    float4 acc = make_float4(0.f,0.f,0.f,0.f);
    float wsum = 0.f;
    for (int base = 0; base < deg; base += 32){
        int cnt = deg - base; if (cnt > 32) cnt = 32;
        int idx = 0; float w = 0.f;
        if (lane < cnt){
            idx = g_isorted[eb + base + lane];
            float2 sd = *(const float2*)&sdb[idx*2];
            float es = 0.5f*(fmaxf(ss.x+sd.x,0.f) + fmaxf(ss.y+sd.y,0.f));
            w = __expf(es);
        }
        wsum += w;
        // 2 edges per step (one per half-warp): 2 float4 rows in flight (8 regs)
        for (int p = 0; p < cnt; p += 4){
            int im0, im1; float wm0, wm1;
            {
                int e0 = p + g;
                int ec0 = (e0 < cnt) ? e0 : 0;
                im0 = __shfl_sync(0xffffffffu, idx, ec0);
                float wv0 = __shfl_sync(0xffffffffu, w, ec0);
                wm0 = (e0 < cnt) ? wv0 : 0.f;
                int e1 = p + 2 + g;
                int ec1 = (e1 < cnt) ? e1 : 0;
                im1 = __shfl_sync(0xffffffffu, idx, ec1);
                float wv1 = __shfl_sync(0xffffffffu, w, ec1);
                wm1 = (e1 < cnt) ? wv1 : 0.f;
            }
            float4 v0 = *(const float4*)&de[im0*64 + d*4];
            float4 v1 = *(const float4*)&de[im1*64 + d*4];
            acc.x = fmaf(wm0, v0.x, acc.x); acc.y = fmaf(wm0, v0.y, acc.y);
            acc.z = fmaf(wm0, v0.z, acc.z); acc.w = fmaf(wm0, v0.w, acc.w);
            acc.x = fmaf(wm1, v1.x, acc.x); acc.y = fmaf(wm1, v1.y, acc.y);
            acc.z = fmaf(wm1, v1.z, acc.z); acc.w = fmaf(wm1, v1.w, acc.w);
        }
    }
    acc.x += __shfl_xor_sync(0xffffffffu, acc.x, 16);
    acc.y += __shfl_xor_sync(0xffffffffu, acc.y, 16);
    acc.z += __shfl_xor_sync(0xffffffffu, acc.z, 16);
    acc.w += __shfl_xor_sync(0xffffffffu, acc.w, 16);
    #pragma unroll
    for (int o=16;o;o>>=1) wsum += __shfl_xor_sync(0xffffffffu, wsum, o);
    float inv = (deg > 0) ? __fdividef(1.f, wsum) : 0.f;
    int sl = (basel >> 1) + ((lane&15) >> 1);
    float b0 = __shfl_sync(0xffffffffu, acc.x, sl);
    float b1 = __shfl_sync(0xffffffffu, acc.y, sl);
    float b2 = __shfl_sync(0xffffffffu, acc.z, sl);
    float b3 = __shfl_sync(0xffffffffu, acc.w, sl);
    float zx = (lane&1) ? b2 : b0;
    float zy = (lane&1) ? b3 : b1;
    float ax = lrelu(zx*inv), ay = lrelu(zy*inv);

    // transform: o = lrelu(z) @ W via packed f32x2 FFMA (W pairs read as 8B LDS)
    ull od = 0ULL;
    #pragma unroll
    for (int c=0;c<32;c++){
        float zc = __shfl_sync(0xffffffffu, (c&1)? ay : ax, basel + (c>>1));
        ull zz;
        asm("mov.b64 %0, {%1, %2};" : "=l"(zz)
            : "r"(__float_as_uint(zc)), "r"(__float_as_uint(zc)));
        ull wv = *(const ull*)&sW[c*32 + col];
        asm("fma.rn.f32x2 %0, %1, %2, %0;" : "+l"(od) : "l"(zz), "l"(wv));
    }
    unsigned oxu, oyu;
    asm("mov.b64 {%0, %1}, %2;" : "=r"(oxu), "=r"(oyu) : "l"(od));
    float ox = __uint_as_float(oxu), oy = __uint_as_float(oyu);

    // r = softmax_k( tanh(o) . q[rel] )
    float tt = tanh_f(ox)*__ldg(&q[rel*32+col]) + tanh_f(oy)*__ldg(&q[rel*32+col+1]);
    #pragma unroll
    for (int o=8;o;o>>=1) tt += __shfl_xor_sync(0xffffffffu, tt, o);
    float to = __shfl_xor_sync(0xffffffffu, tt, 16);
    float r = __fdividef(1.f, 1.f + __expf(to - tt));

    if (wl < 7){
        sZ[wl][lane*2]   = r*ox;
        sZ[wl][lane*2+1] = r*oy;
    } else {
        // finalize type-0 node n BEFORE the barrier (overlaps with other warps)
        float2 e = *(const float2*)&g_embD[cur][n*64 + lane*2];
        e.x = fmaf(ox, r, e.x);
        e.y = fmaf(oy, r, e.y);
        float s = e.x*e.x + e.y*e.y;
        #pragma unroll
        for (int o=8;o;o>>=1) s += __shfl_xor_sync(0xffffffffu, s, o);
        float dinv = __fdividef(1.f, fmaxf(sqrtf(s), 1e-12f));
        e.x *= dinv; e.y *= dinv;
        *(float2*)&g_embD[nxt][n*64 + lane*2] = e;
        if (last){
            *(float2*)&out[(ll)n*64 + lane*2] = e;
        } else {
            float p0 = e.x*__ldg(&at[k*64+col])        + e.y*__ldg(&at[k*64+col+1]);
            float p1 = e.x*__ldg(&at[(2+k)*64+32+col]) + e.y*__ldg(&at[(2+k)*64+32+col+1]);
            #pragma unroll
            for (int o=8;o;o>>=1){
                p0 += __shfl_xor_sync(0xffffffffu, p0, o);
                p1 += __shfl_xor_sync(0xffffffffu, p1, o);
            }
            if ((lane&15) == 0){
                g_ssrc[nxt][n*2 + k]         = p0;
                g_sdstD[nxt][NU*2 + n*2 + k] = p1;
            }
        }
    }
    __syncthreads();
    if (wl == 0){
        // finalize type-1 node n
        float2 e = *(const float2*)&g_embD[cur][(NU+n)*64 + lane*2];
        #pragma unroll
        for (int j=0;j<7;j++){
            e.x += sZ[j][lane*2];
            e.y += sZ[j][lane*2+1];
        }
        float s = e.x*e.x + e.y*e.y;
        #pragma unroll
        for (int o=8;o;o>>=1) s += __shfl_xor_sync(0xffffffffu, s, o);
        float dinv = __fdividef(1.f, fmaxf(sqrtf(s), 1e-12f));
        e.x *= dinv; e.y *= dinv;
        *(float2*)&g_embD[nxt][(NU+n)*64 + lane*2] = e;
        if (last){
            *(float2*)&out[(ll)(NU+n)*64 + lane*2] = e;
        } else {
            float p[8];
            p[0] = e.x*__ldg(&at[k*64+32+col]) + e.y*__ldg(&at[k*64+32+col+1]);
            #pragma unroll
            for (int rl=1; rl<8; rl++)
                p[rl] = e.x*__ldg(&at[(rl*2+k)*64+col]) + e.y*__ldg(&at[(rl*2+k)*64+col+1]);
            #pragma unroll
            for (int rl=0; rl<8; rl++){
                #pragma unroll
                for (int o=8;o;o>>=1) p[rl] += __shfl_xor_sync(0xffffffffu, p[rl], o);
            }
            if ((lane&15) == 0){
                g_sdstD[nxt][n*2 + k] = p[0];
                #pragma unroll
                for (int rl=1; rl<8; rl++) g_ssrc[nxt][(rl*NU+n)*2 + k] = p[rl];
            }
        }
    }
}

// reset counts/cursor for the next invocation (first call relies on static zero-init)
__global__ void k_rezero(){
    int i = blockIdx.x*blockDim.x + threadIdx.x;
    if (i < NREL*NU){ g_counts[i]=0; g_cursor[i]=0; }
}

// ---------------- launch ----------------
extern "C" void kernel_launch(void* const* d_in, const int* in_sizes, int n_in,
                              void* d_out, int out_size) {
    const float* emb[8];
    for (int t=0;t<8;t++) emb[t] = (const float*)d_in[t];
    const int* u[8]; const int* ia[8];
    for (int e=0;e<8;e++){
        u[e]  = (const int*)d_in[8 + 2*e];
        ia[e] = (const int*)d_in[9 + 2*e];
    }
    const float* Wtk = (const float*)d_in[24];
    const float* at  = (const float*)d_in[25];
    const float* W   = (const float*)d_in[26];
    const float* q   = (const float*)d_in[27];
    float* out = (float*)d_out;

    k_count_all<<<(ETOT+255)/256, 256>>>(u[0],u[1],u[2],u[3],u[4],u[5],u[6],u[7]);
    k_scan<<<8, 1024>>>();
    k_scatter_all<<<(ETOT+255)/256, 256>>>(u[0],u[1],u[2],u[3],u[4],u[5],u[6],u[7],
                                           ia[0],ia[1],ia[2],ia[3],ia[4],ia[5],ia[6],ia[7]);
    k_proj<<<2506, 256>>>(emb[0],emb[1],emb[2],emb[3],emb[4],emb[5],emb[6],emb[7], Wtk);
    k_dots0<<<70000, 256>>>(at);

    for (int it=0; it<4; it++)
        k_iter<<<50938, 256>>>(W, q, at, it & 1, it == 3, out);

    k_rezero<<<(NREL*NU + 255)/256, 256>>>();
}

// round 15
// speedup vs baseline: 1.8250x; 1.8250x over previous
#include <cuda_runtime.h>

#define NREL 8
#define NU   50000
#define ETOT 3400000
typedef long long ll;
typedef unsigned long long ull;

__constant__ int c_N[8]       = {50000,50000,10000,10000,10000,10000,10000,10000};
__constant__ int c_edgeoff[8] = {0,800000,1600000,1900000,2200000,2500000,2800000,3100000};
__constant__ int c_chunkoff[8]= {0,782,1564,1721,1878,2035,2192,2349};

// dynamic (types 0/1) double-buffered; static (types 2-7) single copy
__device__ float g_embD[2][100000*64];
__device__ float g_embS[60000*64];
__device__ float g_ssrc[2][NREL*NU*2];
__device__ float g_sdstD[2][2*NU*2];
__device__ float g_sdstS[60000*2];
__device__ int   g_rowptr[NREL*(NU+1)];
__device__ int   g_counts[NREL*NU];   // zero at load; re-zeroed by k_rezero each call
__device__ int   g_cursor[NREL*NU];
__device__ int   g_isorted[ETOT];
__device__ int   g_usorted[ETOT];
__device__ float g_w[ETOT];           // per-edge exp(logit), rebuilt each iteration

__device__ __forceinline__ float lrelu(float x){ return x > 0.f ? x : 0.2f*x; }
__device__ __forceinline__ float tanh_f(float x){
    float y; asm("tanh.approx.f32 %0, %1;" : "=f"(y) : "f"(x)); return y;
}

// ---------------- setup ----------------
__global__ void k_count_all(const int* __restrict__ u0, const int* __restrict__ u1,
                            const int* __restrict__ u2, const int* __restrict__ u3,
                            const int* __restrict__ u4, const int* __restrict__ u5,
                            const int* __restrict__ u6, const int* __restrict__ u7){
    int t = blockIdx.x*blockDim.x + threadIdx.x;
    if (t >= ETOT) return;
    int rel = 0;
    #pragma unroll
    for (int j=1;j<8;j++) if (t >= c_edgeoff[j]) rel = j;
    const int* up;
    switch (rel){
        case 0: up=u0; break; case 1: up=u1; break; case 2: up=u2; break; case 3: up=u3; break;
        case 4: up=u4; break; case 5: up=u5; break; case 6: up=u6; break; default: up=u7; break;
    }
    atomicAdd(&g_counts[rel*NU + up[t - c_edgeoff[rel]]], 1);
}

__global__ void k_scan(){
    __shared__ int sm[1024];
    int rel = blockIdx.x, t = threadIdx.x;
    const int n = NU, CH = 49;
    int* cnt = g_counts + rel*NU;
    int* rp  = g_rowptr + rel*(NU+1);
    int c0 = t*CH, c1 = min(c0+CH, n);
    int s = 0;
    for (int i=c0;i<c1;i++) s += cnt[i];
    sm[t] = s; __syncthreads();
    for (int off=1; off<1024; off<<=1){
        int v = (t>=off)? sm[t-off] : 0;
        __syncthreads();
        sm[t] += v;
        __syncthreads();
    }
    int run = sm[t] - s;
    for (int i=c0;i<c1;i++){ rp[i]=run; run+=cnt[i]; }
    if (t==0) rp[n] = sm[1023];
}

__global__ void k_scatter_all(const int* __restrict__ u0, const int* __restrict__ u1,
                              const int* __restrict__ u2, const int* __restrict__ u3,
                              const int* __restrict__ u4, const int* __restrict__ u5,
                              const int* __restrict__ u6, const int* __restrict__ u7,
                              const int* __restrict__ i0, const int* __restrict__ i1,
                              const int* __restrict__ i2, const int* __restrict__ i3,
                              const int* __restrict__ i4, const int* __restrict__ i5,
                              const int* __restrict__ i6, const int* __restrict__ i7){
    int t = blockIdx.x*blockDim.x + threadIdx.x;
    if (t >= ETOT) return;
    int rel = 0;
    #pragma unroll
    for (int j=1;j<8;j++) if (t >= c_edgeoff[j]) rel = j;
    const int *up, *ip;
    switch (rel){
        case 0: up=u0; ip=i0; break; case 1: up=u1; ip=i1; break;
        case 2: up=u2; ip=i2; break; case 3: up=u3; ip=i3; break;
        case 4: up=u4; ip=i4; break; case 5: up=u5; ip=i5; break;
        case 6: up=u6; ip=i6; break; default: up=u7; ip=i7; break;
    }
    int e = t - c_edgeoff[rel];
    int uu = up[e];
    int pos = g_rowptr[rel*(NU+1)+uu] + atomicAdd(&g_cursor[rel*NU+uu], 1);
    g_isorted[c_edgeoff[rel] + pos] = ip[e];
    g_usorted[c_edgeoff[rel] + pos] = uu;
}

// initial projection: l2norm(lrelu(emb_t @ Wtk[t][k]))
__global__ void __launch_bounds__(256) k_proj(
    const float* __restrict__ e0, const float* __restrict__ e1,
    const float* __restrict__ e2, const float* __restrict__ e3,
    const float* __restrict__ e4, const float* __restrict__ e5,
    const float* __restrict__ e6, const float* __restrict__ e7,
    const float* __restrict__ Wtk)
{
    __shared__ float sW[4096];
    __shared__ float sE[4096];
    int b = blockIdx.x;
    int t = 0;
    #pragma unroll
    for (int j=1;j<8;j++) if (b >= c_chunkoff[j]) t = j;
    int n0 = (b - c_chunkoff[t]) * 64;
    const float* embp;
    switch (t){
        case 0: embp=e0; break; case 1: embp=e1; break;
        case 2: embp=e2; break; case 3: embp=e3; break;
        case 4: embp=e4; break; case 5: embp=e5; break;
        case 6: embp=e6; break; default: embp=e7; break;
    }
    int Nt = c_N[t], tid = threadIdx.x;
    for (int i=tid;i<4096;i+=256) sW[i] = Wtk[t*4096 + i];
    for (int i=tid;i<4096;i+=256){
        int n = n0 + (i>>6);
        sE[i] = (n < Nt) ? embp[(ll)n*64 + (i&63)] : 0.f;
    }
    __syncthreads();
    int lane = tid&31, w = tid>>5;
    float acc0[8], acc1[8];
    #pragma unroll
    for (int q=0;q<8;q++){ acc0[q]=0.f; acc1[q]=0.f; }
    #pragma unroll 4
    for (int c=0;c<64;c++){
        float w0 = sW[c*32+lane];
        float w1 = sW[2048+c*32+lane];
        #pragma unroll
        for (int q=0;q<8;q++){
            float e = sE[(w*8+q)*64 + c];
            acc0[q] = fmaf(e,w0,acc0[q]);
            acc1[q] = fmaf(e,w1,acc1[q]);
        }
    }
    #pragma unroll
    for (int q=0;q<8;q++){
        int n = n0 + w*8 + q;
        if (n >= Nt) continue;
        float y0 = lrelu(acc0[q]), y1 = lrelu(acc1[q]);
        float s0 = y0*y0, s1 = y1*y1;
        #pragma unroll
        for (int o=16;o;o>>=1){
            s0 += __shfl_xor_sync(0xffffffffu, s0, o);
            s1 += __shfl_xor_sync(0xffffffffu, s1, o);
        }
        float d0 = fmaxf(sqrtf(s0), 1e-12f);
        float d1 = fmaxf(sqrtf(s1), 1e-12f);
        float* dst;
        if (t < 2) dst = &g_embD[0][(t*NU + n)*64];
        else       dst = &g_embS[((t-2)*10000 + n)*64];
        dst[lane]      = y0 / d0;
        dst[32 + lane] = y1 / d1;
    }
}

// initial per-node attention dot halves (gen-0)
__global__ void k_dots0(const float* __restrict__ at){
    int lane = threadIdx.x & 31;
    int gw = (blockIdx.x*blockDim.x + threadIdx.x) >> 5;
    int k = lane >> 4, col = (lane&15)*2;
    float2 e; const float* ap; float* outp;
    if (gw < 400000){
        int rel = gw / NU, n = gw - rel*NU;
        int type = rel ? 1 : 0;
        e = *(const float2*)&g_embD[0][(type*NU+n)*64 + lane*2];
        ap = &at[(rel*2+k)*64 + col];
        outp = &g_ssrc[0][(rel*NU+n)*2 + k];
    } else if (gw < 450000){
        int n = gw - 400000;
        e = *(const float2*)&g_embD[0][(NU+n)*64 + lane*2];
        ap = &at[(0*2+k)*64 + 32 + col];
        outp = &g_sdstD[0][n*2 + k];
    } else if (gw < 500000){
        int n = gw - 450000;
        e = *(const float2*)&g_embD[0][n*64 + lane*2];
        ap = &at[(1*2+k)*64 + 32 + col];
        outp = &g_sdstD[0][NU*2 + n*2 + k];
    } else {
        int m = gw - 500000;
        e = *(const float2*)&g_embS[m*64 + lane*2];
        int rel = 2 + m/10000;
        ap = &at[(rel*2+k)*64 + 32 + col];
        outp = &g_sdstS[m*2 + k];
    }
    float p = e.x*__ldg(&ap[0]) + e.y*__ldg(&ap[1]);
    p += __shfl_xor_sync(0xffffffffu, p, 8);
    p += __shfl_xor_sync(0xffffffffu, p, 4);
    p += __shfl_xor_sync(0xffffffffu, p, 2);
    p += __shfl_xor_sync(0xffffffffu, p, 1);
    if ((lane&15) == 0) *outp = p;
}

// ---------------- per-iteration edge weights (flat, high-MLP) ----------------
__global__ void __launch_bounds__(256) k_wt(int cur){
    int t = blockIdx.x*blockDim.x + threadIdx.x;
    if (t >= ETOT) return;
    int rel = 0;
    #pragma unroll
    for (int j=1;j<8;j++) if (t >= c_edgeoff[j]) rel = j;
    const float* sdb;
    if (rel == 0)      sdb = &g_sdstD[cur][0];
    else if (rel == 1) sdb = &g_sdstD[cur][NU*2];
    else               sdb = &g_sdstS[(rel-2)*10000*2];
    int i = g_isorted[t];
    int u = g_usorted[t];
    float2 ss = *(const float2*)&g_ssrc[cur][(rel*NU+u)*2];
    float2 sd = *(const float2*)&sdb[i*2];
    float es = 0.5f*(fmaxf(ss.x+sd.x,0.f) + fmaxf(ss.y+sd.y,0.f));
    g_w[t] = __expf(es);
}

// ---------------- fused iteration: block = node pair, warp = relation ----------------
__global__ void __launch_bounds__(256) k_iter(const float* __restrict__ W,
                                              const float* __restrict__ q,
                                              const float* __restrict__ at,
                                              int cur, int last,
                                              float* __restrict__ out){
    if (blockIdx.x >= 50000){
        if (!last) return;
        // static types copy to output rows 100000..159999
        int base = (blockIdx.x - 50000)*1024 + threadIdx.x;
        float4* o4 = (float4*)(out + (ll)100000*64);
        #pragma unroll
        for (int j=0;j<4;j++){
            int i = base + j*256;
            if (i < 960000) o4[i] = ((const float4*)g_embS)[i];
        }
        return;
    }
    __shared__ float sW[1024];
    __shared__ float sZ[7][64];
    int tid = threadIdx.x;
    for (int i=tid;i<1024;i+=256) sW[i] = W[i];
    __syncthreads();
    int lane = tid&31, wl = tid>>5;
    int n = blockIdx.x;
    int nxt = cur ^ 1;
    int k = lane>>4, col = (lane&15)*2, basel = lane & 16;

    int rel = (wl == 7) ? 0 : (wl + 1);
    const float *de;
    if (rel == 0)      de = &g_embD[cur][NU*64];
    else if (rel == 1) de = &g_embD[cur][0];
    else               de = &g_embS[(rel-2)*10000*64];

    int rb = rel*(NU+1) + n;
    int row = g_rowptr[rb], deg = g_rowptr[rb+1] - row;
    int eb = c_edgeoff[rel] + row;

    int g = lane >> 4, d = lane & 15;
    float4 acc = make_float4(0.f,0.f,0.f,0.f);
    float wsum = 0.f;
    for (int base = 0; base < deg; base += 32){
        int cnt = deg - base; if (cnt > 32) cnt = 32;
        int idx = 0; float w = 0.f;
        if (lane < cnt){
            idx = g_isorted[eb + base + lane];
            w   = g_w[eb + base + lane];
        }
        wsum += w;
        for (int p = 0; p < cnt; p += 8){
            int im[4]; float wm[4];
            #pragma unroll
            for (int m=0;m<4;m++){
                int e = p + 2*m + g;
                int ec = (e < cnt) ? e : 0;
                im[m] = __shfl_sync(0xffffffffu, idx, ec);
                float wv = __shfl_sync(0xffffffffu, w, ec);
                wm[m] = (e < cnt) ? wv : 0.f;
            }
            float4 v0 = *(const float4*)&de[im[0]*64 + d*4];
            float4 v1 = *(const float4*)&de[im[1]*64 + d*4];
            float4 v2 = *(const float4*)&de[im[2]*64 + d*4];
            float4 v3 = *(const float4*)&de[im[3]*64 + d*4];
            acc.x = fmaf(wm[0], v0.x, acc.x); acc.y = fmaf(wm[0], v0.y, acc.y);
            acc.z = fmaf(wm[0], v0.z, acc.z); acc.w = fmaf(wm[0], v0.w, acc.w);
            acc.x = fmaf(wm[1], v1.x, acc.x); acc.y = fmaf(wm[1], v1.y, acc.y);
            acc.z = fmaf(wm[1], v1.z, acc.z); acc.w = fmaf(wm[1], v1.w, acc.w);
            acc.x = fmaf(wm[2], v2.x, acc.x); acc.y = fmaf(wm[2], v2.y, acc.y);
            acc.z = fmaf(wm[2], v2.z, acc.z); acc.w = fmaf(wm[2], v2.w, acc.w);
            acc.x = fmaf(wm[3], v3.x, acc.x); acc.y = fmaf(wm[3], v3.y, acc.y);
            acc.z = fmaf(wm[3], v3.z, acc.z); acc.w = fmaf(wm[3], v3.w, acc.w);
        }
    }
    acc.x += __shfl_xor_sync(0xffffffffu, acc.x, 16);
    acc.y += __shfl_xor_sync(0xffffffffu, acc.y, 16);
    acc.z += __shfl_xor_sync(0xffffffffu, acc.z, 16);
    acc.w += __shfl_xor_sync(0xffffffffu, acc.w, 16);
    #pragma unroll
    for (int o=16;o;o>>=1) wsum += __shfl_xor_sync(0xffffffffu, wsum, o);
    float inv = (deg > 0) ? __fdividef(1.f, wsum) : 0.f;
    int sl = (basel >> 1) + ((lane&15) >> 1);
    float b0 = __shfl_sync(0xffffffffu, acc.x, sl);
    float b1 = __shfl_sync(0xffffffffu, acc.y, sl);
    float b2 = __shfl_sync(0xffffffffu, acc.z, sl);
    float b3 = __shfl_sync(0xffffffffu, acc.w, sl);
    float zx = (lane&1) ? b2 : b0;
    float zy = (lane&1) ? b3 : b1;
    float ax = lrelu(zx*inv), ay = lrelu(zy*inv);

    // transform: o = lrelu(z) @ W via packed f32x2 FFMA (W pairs read as 8B LDS)
    ull od = 0ULL;
    #pragma unroll
    for (int c=0;c<32;c++){
        float zc = __shfl_sync(0xffffffffu, (c&1)? ay : ax, basel + (c>>1));
        ull zz;
        asm("mov.b64 %0, {%1, %2};" : "=l"(zz)
            : "r"(__float_as_uint(zc)), "r"(__float_as_uint(zc)));
        ull wv = *(const ull*)&sW[c*32 + col];
        asm("fma.rn.f32x2 %0, %1, %2, %0;" : "+l"(od) : "l"(zz), "l"(wv));
    }
    unsigned oxu, oyu;
    asm("mov.b64 {%0, %1}, %2;" : "=r"(oxu), "=r"(oyu) : "l"(od));
    float ox = __uint_as_float(oxu), oy = __uint_as_float(oyu);

    // r = softmax_k( tanh(o) . q[rel] )
    float tt = tanh_f(ox)*__ldg(&q[rel*32+col]) + tanh_f(oy)*__ldg(&q[rel*32+col+1]);
    #pragma unroll
    for (int o=8;o;o>>=1) tt += __shfl_xor_sync(0xffffffffu, tt, o);
    float to = __shfl_xor_sync(0xffffffffu, tt, 16);
    float r = __fdividef(1.f, 1.f + __expf(to - tt));

    if (wl < 7){
        sZ[wl][lane*2]   = r*ox;
        sZ[wl][lane*2+1] = r*oy;
    } else {
        // finalize type-0 node n BEFORE the barrier (overlaps with other warps)
        float2 e = *(const float2*)&g_embD[cur][n*64 + lane*2];
        e.x = fmaf(ox, r, e.x);
        e.y = fmaf(oy, r, e.y);
        float s = e.x*e.x + e.y*e.y;
        #pragma unroll
        for (int o=8;o;o>>=1) s += __shfl_xor_sync(0xffffffffu, s, o);
        float dinv = __fdividef(1.f, fmaxf(sqrtf(s), 1e-12f));
        e.x *= dinv; e.y *= dinv;
        *(float2*)&g_embD[nxt][n*64 + lane*2] = e;
        if (last){
            *(float2*)&out[(ll)n*64 + lane*2] = e;
        } else {
            float p0 = e.x*__ldg(&at[k*64+col])        + e.y*__ldg(&at[k*64+col+1]);
            float p1 = e.x*__ldg(&at[(2+k)*64+32+col]) + e.y*__ldg(&at[(2+k)*64+32+col+1]);
            #pragma unroll
            for (int o=8;o;o>>=1){
                p0 += __shfl_xor_sync(0xffffffffu, p0, o);
                p1 += __shfl_xor_sync(0xffffffffu, p1, o);
            }
            if ((lane&15) == 0){
                g_ssrc[nxt][n*2 + k]         = p0;
                g_sdstD[nxt][NU*2 + n*2 + k] = p1;
            }
        }
    }
    __syncthreads();
    if (wl == 0){
        // finalize type-1 node n
        float2 e = *(const float2*)&g_embD[cur][(NU+n)*64 + lane*2];
        #pragma unroll
        for (int j=0;j<7;j++){
            e.x += sZ[j][lane*2];
            e.y += sZ[j][lane*2+1];
        }
        float s = e.x*e.x + e.y*e.y;
        #pragma unroll
        for (int o=8;o;o>>=1) s += __shfl_xor_sync(0xffffffffu, s, o);
        float dinv = __fdividef(1.f, fmaxf(sqrtf(s), 1e-12f));
        e.x *= dinv; e.y *= dinv;
        *(float2*)&g_embD[nxt][(NU+n)*64 + lane*2] = e;
        if (last){
            *(float2*)&out[(ll)(NU+n)*64 + lane*2] = e;
        } else {
            float p[8];
            p[0] = e.x*__ldg(&at[k*64+32+col]) + e.y*__ldg(&at[k*64+32+col+1]);
            #pragma unroll
            for (int rl=1; rl<8; rl++)
                p[rl] = e.x*__ldg(&at[(rl*2+k)*64+col]) + e.y*__ldg(&at[(rl*2+k)*64+col+1]);
            #pragma unroll
            for (int rl=0; rl<8; rl++){
                #pragma unroll
                for (int o=8;o;o>>=1) p[rl] += __shfl_xor_sync(0xffffffffu, p[rl], o);
            }
            if ((lane&15) == 0){
                g_sdstD[nxt][n*2 + k] = p[0];
                #pragma unroll
                for (int rl=1; rl<8; rl++) g_ssrc[nxt][(rl*NU+n)*2 + k] = p[rl];
            }
        }
    }
}

// reset counts/cursor for the next invocation (first call relies on static zero-init)
__global__ void k_rezero(){
    int i = blockIdx.x*blockDim.x + threadIdx.x;
    if (i < NREL*NU){ g_counts[i]=0; g_cursor[i]=0; }
}

// ---------------- launch ----------------
extern "C" void kernel_launch(void* const* d_in, const int* in_sizes, int n_in,
                              void* d_out, int out_size) {
    const float* emb[8];
    for (int t=0;t<8;t++) emb[t] = (const float*)d_in[t];
    const int* u[8]; const int* ia[8];
    for (int e=0;e<8;e++){
        u[e]  = (const int*)d_in[8 + 2*e];
        ia[e] = (const int*)d_in[9 + 2*e];
    }
    const float* Wtk = (const float*)d_in[24];
    const float* at  = (const float*)d_in[25];
    const float* W   = (const float*)d_in[26];
    const float* q   = (const float*)d_in[27];
    float* out = (float*)d_out;

    k_count_all<<<(ETOT+255)/256, 256>>>(u[0],u[1],u[2],u[3],u[4],u[5],u[6],u[7]);
    k_scan<<<8, 1024>>>();
    k_scatter_all<<<(ETOT+255)/256, 256>>>(u[0],u[1],u[2],u[3],u[4],u[5],u[6],u[7],
                                           ia[0],ia[1],ia[2],ia[3],ia[4],ia[5],ia[6],ia[7]);
    k_proj<<<2506, 256>>>(emb[0],emb[1],emb[2],emb[3],emb[4],emb[5],emb[6],emb[7], Wtk);
    k_dots0<<<70000, 256>>>(at);

    for (int it=0; it<4; it++){
        k_wt<<<(ETOT+255)/256, 256>>>(it & 1);
        k_iter<<<50938, 256>>>(W, q, at, it & 1, it == 3, out);
    }

    k_rezero<<<(NREL*NU + 255)/256, 256>>>();
}